// round 16
// baseline (speedup 1.0000x reference)
#include <cuda_runtime.h>
#include <cuda_bf16.h>
#include <math.h>

#define BATCH 8192
#define DIM   512
#define NREG  4
#define NS    6
#define HIDN  128
#define NHEAD 4
#define HD    128
#define KEXT  544                 // 512 coeffs + 6 ww + 26 pad (32-divisible)
#define MEXT  640                 // Apack rows: 512 Wp + 6 bp + 122 pad

// db8 lowpass (pywt 'periodization')
__constant__ float c_lo[16] = {
    -0.00011747678400228192f, 0.0006754494059985568f, -0.0003917403729959771f,
    -0.00487035299301066f,    0.008746094047015655f,  0.013981027917015516f,
    -0.04408825393106472f,    -0.01736930100202211f,  0.128747426620186f,
    0.00047248457399797254f,  -0.2840155429624281f,   -0.015829105256023893f,
    0.5853546836548691f,      0.6756307362980128f,    0.3128715909144659f,
    0.05441584224308161f
};

__constant__ int c_off[NS] = {0, 16, 32, 64, 128, 256};
__constant__ int c_len[NS] = {16, 16, 32, 64, 128, 256};
// LPT order for qk z-slices (descending K): (t, s) pairs
__constant__ int z_t[12] = {0, 1, 0, 1, 0, 1, 0, 1, 0, 1, 0, 1};
__constant__ int z_s[12] = {5, 5, 4, 4, 3, 3, 2, 2, 1, 1, 0, 0};

// ---- scratch ----
__device__ __nv_bfloat16 g_coeffsb[BATCH * DIM];
__device__ __nv_bfloat16 g_xb[BATCH * DIM];
__device__ float g_logits[BATCH * NREG * NS];
__device__ float g_W1cat[DIM * DIM];
__device__ float g_biasH[DIM];
__device__ float g_Apack[MEXT * DIM];
__device__ float g_WfE[3 * MEXT * DIM];
__device__ float g_biasf[2 * NS * DIM];
__device__ __nv_bfloat16 g_WfT[2 * DIM * DIM];
__device__ __nv_bfloat16 g_W1catT[DIM * DIM];
__device__ __nv_bfloat16 g_WfvT[DIM * KEXT];
__device__ __nv_bfloat16 g_WoT[DIM * DIM];
__device__ __nv_bfloat16 g_Qb[BATCH * NS * DIM];
__device__ __nv_bfloat16 g_Kb[BATCH * NS * DIM];
__device__ __nv_bfloat16 g_csb[(size_t)BATCH * NHEAD * KEXT];
__device__ __nv_bfloat16 g_preb[BATCH * DIM];
__device__ float g_agg[BATCH * DIM];

// =====================================================================
// 1) DWT: warp-per-row
// =====================================================================
__global__ __launch_bounds__(128) void dwt_kernel(
    const float* __restrict__ x,
    __nv_bfloat16* __restrict__ coeffsb,
    __nv_bfloat16* __restrict__ xb)
{
    __shared__ float sbuf[4][768];
    int w = threadIdx.x >> 5, lane = threadIdx.x & 31;
    int b = blockIdx.x * 4 + w;
    float* buf512 = sbuf[w];
    float* buf256 = sbuf[w] + 512;

    const float4* xr = (const float4*)(x + (size_t)b * DIM);
    __nv_bfloat162* xbw = (__nv_bfloat162*)(xb + (size_t)b * DIM);
    #pragma unroll
    for (int i = lane; i < 128; i += 32) {
        float4 v = xr[i];
        buf512[i * 4 + 0] = v.x;
        buf512[i * 4 + 1] = v.y;
        buf512[i * 4 + 2] = v.z;
        buf512[i * 4 + 3] = v.w;
        xbw[i * 2 + 0] = __floats2bfloat162_rn(v.x, v.y);
        xbw[i * 2 + 1] = __floats2bfloat162_rn(v.z, v.w);
    }
    __syncwarp();

    float* src = buf512;
    float* dst = buf256;
    int n = DIM;
    for (int lev = 0; lev < 5; lev++) {
        int nh = n >> 1;
        for (int k = lane; k < nh; k += 32) {
            float sa = 0.f, sd = 0.f;
            #pragma unroll
            for (int j = 0; j < 16; j++) {
                int m = 2 * k + 1 - j;
                if (m < 0) m += n;
                float av = src[m];
                float hj = c_lo[15 - j] * ((j & 1) ? 1.f : -1.f);
                sa += c_lo[j] * av;
                sd += hj * av;
            }
            dst[k] = sa;
            coeffsb[(size_t)b * DIM + nh + k] = __float2bfloat16(sd);
        }
        __syncwarp();
        float* t = src; src = dst; dst = t;
        n = nh;
    }
    for (int k = lane; k < 16; k += 32)
        coeffsb[(size_t)b * DIM + k] = __float2bfloat16(src[k]);
}

// =====================================================================
// 2) weight repacking
// =====================================================================
__global__ void prep_pack(const float* __restrict__ W1, const float* __restrict__ b1,
                          const float* __restrict__ Wp, const float* __restrict__ bp,
                          float* __restrict__ W1cat, float* __restrict__ biasH,
                          float* __restrict__ Apack)
{
    int row = blockIdx.x;
    int c   = threadIdx.x;
    int r = c >> 7, j = c & 127;

    float av;
    if (row < 512) {
        W1cat[row * DIM + c] = W1[r * (516 * 128) + row * 128 + j];
        int s, k;
        if      (row < 16)  { s = 0; k = row;       }
        else if (row < 32)  { s = 1; k = row - 16;  }
        else if (row < 64)  { s = 2; k = row - 32;  }
        else if (row < 128) { s = 3; k = row - 64;  }
        else if (row < 256) { s = 4; k = row - 128; }
        else                { s = 5; k = row - 256; }
        av = Wp[s * (DIM * DIM) + k * DIM + c];
        if (row == 0)
            biasH[c] = b1[r * 128 + j] + W1[r * (516 * 128) + (512 + r) * 128 + j];
    } else if (row < 518) {
        av = bp[(row - 512) * DIM + c];
    } else {
        av = 0.f;
    }
    Apack[row * DIM + c] = av;
}

// tiled transpose + bf16 (5 jobs) + bias finishing lane (blockIdx.y == 16)
__global__ void transp_jobs(const float* __restrict__ WfE, const float* __restrict__ W1cat,
                            const float* __restrict__ Wo,
                            const float* __restrict__ bq, const float* __restrict__ bk,
                            const float* __restrict__ bv,
                            __nv_bfloat16* __restrict__ WfT,
                            __nv_bfloat16* __restrict__ W1catT,
                            __nv_bfloat16* __restrict__ WfvT,
                            __nv_bfloat16* __restrict__ WoT,
                            float* __restrict__ biasf)
{
    int job = blockIdx.z;
    if (blockIdx.y == 16) {
        int d = blockIdx.x * 32 + threadIdx.x;
        if (job == 0 || job == 1) {
            const float* bvec = (job == 0) ? bq : bk;
            for (int s = threadIdx.y; s < NS; s += 8)
                biasf[(job * NS + s) * DIM + d] =
                    WfE[(size_t)job * MEXT * DIM + (size_t)(512 + s) * DIM + d] + bvec[d];
        } else if (job == 3) {
            for (int i = threadIdx.y; i < 32; i += 8) {
                float v = 0.f;
                if (i < NS)
                    v = WfE[(size_t)2 * MEXT * DIM + (size_t)(512 + i) * DIM + d] + bv[d];
                WfvT[(size_t)d * KEXT + 512 + i] = __float2bfloat16(v);
            }
        }
        return;
    }

    const float* src;
    __nv_bfloat16* dst;
    int dstStride = DIM;
    switch (job) {
        case 0: src = WfE;                    dst = WfT;             break;
        case 1: src = WfE + MEXT * DIM;       dst = WfT + DIM * DIM; break;
        case 2: src = W1cat;                  dst = W1catT;          break;
        case 3: src = WfE + 2 * MEXT * DIM;   dst = WfvT; dstStride = KEXT; break;
        default: src = Wo;                    dst = WoT;             break;
    }
    __shared__ float tile[32][33];
    int k0 = blockIdx.y * 32, n0 = blockIdx.x * 32;
    for (int i = threadIdx.y; i < 32; i += 8)
        tile[i][threadIdx.x] = src[(size_t)(k0 + i) * DIM + n0 + threadIdx.x];
    __syncthreads();
    for (int i = threadIdx.y; i < 32; i += 8)
        dst[(size_t)(n0 + i) * dstStride + k0 + threadIdx.x] =
            __float2bfloat16(tile[threadIdx.x][i]);
}

// =====================================================================
// 3) tf32 GEMM (Wf prep only)
// =====================================================================
__device__ __forceinline__ void cp16(void* dst, const void* src) {
    unsigned d = (unsigned)__cvta_generic_to_shared(dst);
    asm volatile("cp.async.ca.shared.global [%0], [%1], 16;" :: "r"(d), "l"(src));
}

__device__ __forceinline__ void ldsm4(unsigned& r0, unsigned& r1,
                                      unsigned& r2, unsigned& r3, const void* p) {
    unsigned a = (unsigned)__cvta_generic_to_shared(p);
    asm volatile("ldmatrix.sync.aligned.m8n8.x4.shared.b16 {%0,%1,%2,%3}, [%4];"
                 : "=r"(r0), "=r"(r1), "=r"(r2), "=r"(r3) : "r"(a));
}

__device__ __forceinline__ void gemm_tile(
    const float* __restrict__ A, int lda,
    const float* __restrict__ B, int ldb,
    float* __restrict__ C, int ldc, int K,
    int bm, int bn)
{
    __shared__ float As[2][128][20];
    __shared__ float Bs[2][16][136];
    int t = threadIdx.x;
    int warp = t >> 5, lane = t & 31;
    int wm = (warp >> 2) * 64;
    int wn = (warp & 3) * 32;
    int gid = lane >> 2, tig = lane & 3;

    int aRow = t >> 2, aC = (t & 3) << 2;
    int bRow = t >> 5, bC = (t & 31) << 2;
    const float* Ab = A + (size_t)bm * lda;
    int nk = K >> 4;

    cp16(&As[0][aRow][aC],      &Ab[(size_t)aRow * lda + aC]);
    cp16(&As[0][aRow + 64][aC], &Ab[(size_t)(aRow + 64) * lda + aC]);
    cp16(&Bs[0][bRow][bC],      &B[(size_t)bRow * ldb + bn + bC]);
    cp16(&Bs[0][bRow + 8][bC],  &B[(size_t)(bRow + 8) * ldb + bn + bC]);
    asm volatile("cp.async.commit_group;");

    float c[4][4][4] = {};

    for (int i = 0; i < nk; i++) {
        if (i + 1 < nk) {
            int st = (i + 1) & 1, k0 = (i + 1) << 4;
            cp16(&As[st][aRow][aC],      &Ab[(size_t)aRow * lda + k0 + aC]);
            cp16(&As[st][aRow + 64][aC], &Ab[(size_t)(aRow + 64) * lda + k0 + aC]);
            cp16(&Bs[st][bRow][bC],      &B[(size_t)(k0 + bRow) * ldb + bn + bC]);
            cp16(&Bs[st][bRow + 8][bC],  &B[(size_t)(k0 + bRow + 8) * ldb + bn + bC]);
            asm volatile("cp.async.commit_group;");
            asm volatile("cp.async.wait_group 1;");
        } else {
            asm volatile("cp.async.wait_group 0;");
        }
        __syncthreads();
        int st = i & 1;
        #pragma unroll
        for (int kk = 0; kk < 16; kk += 8) {
            unsigned a[4][4], b[4][2];
            #pragma unroll
            for (int mi = 0; mi < 4; mi++) {
                const float* p = &As[st][wm + mi * 16 + gid][kk + tig];
                a[mi][0] = __float_as_uint(p[0]);
                a[mi][1] = __float_as_uint(p[8 * 20]);
                a[mi][2] = __float_as_uint(p[4]);
                a[mi][3] = __float_as_uint(p[8 * 20 + 4]);
            }
            #pragma unroll
            for (int ni = 0; ni < 4; ni++) {
                const float* p = &Bs[st][kk + tig][wn + ni * 8 + gid];
                b[ni][0] = __float_as_uint(p[0]);
                b[ni][1] = __float_as_uint(p[4 * 136]);
            }
            #pragma unroll
            for (int mi = 0; mi < 4; mi++)
                #pragma unroll
                for (int ni = 0; ni < 4; ni++)
                    asm volatile(
                        "mma.sync.aligned.m16n8k8.row.col.f32.tf32.tf32.f32 "
                        "{%0,%1,%2,%3}, {%4,%5,%6,%7}, {%8,%9}, {%0,%1,%2,%3};"
                        : "+f"(c[mi][ni][0]), "+f"(c[mi][ni][1]),
                          "+f"(c[mi][ni][2]), "+f"(c[mi][ni][3])
                        : "r"(a[mi][0]), "r"(a[mi][1]), "r"(a[mi][2]), "r"(a[mi][3]),
                          "r"(b[ni][0]), "r"(b[ni][1]));
        }
        __syncthreads();
    }

    #pragma unroll
    for (int mi = 0; mi < 4; mi++) {
        int r0 = bm + wm + mi * 16 + gid;
        #pragma unroll
        for (int ni = 0; ni < 4; ni++) {
            int col = bn + wn + ni * 8 + tig * 2;
            *(float2*)&C[(size_t)r0 * ldc + col] =
                make_float2(c[mi][ni][0], c[mi][ni][1]);
            *(float2*)&C[(size_t)(r0 + 8) * ldc + col] =
                make_float2(c[mi][ni][2], c[mi][ni][3]);
        }
    }
}

__global__ __launch_bounds__(256, 2) void gemm_wf(
    const float* __restrict__ Apack,
    const float* __restrict__ Wq, const float* __restrict__ Wk,
    const float* __restrict__ Wv, float* __restrict__ WfE)
{
    int z = blockIdx.z;
    const float* B = (z == 0) ? Wq : (z == 1) ? Wk : Wv;
    float* C = WfE + (size_t)z * MEXT * DIM;
    gemm_tile(Apack, DIM, B, DIM, C, DIM, DIM,
              blockIdx.y * 128, blockIdx.x * 128);
}

// =====================================================================
// 3b) bf16 GEMM mainloop template
// =====================================================================
template<int BK>
__device__ __forceinline__ void bf16_mainloop(
    const __nv_bfloat16* __restrict__ Ab, int lda,
    const __nv_bfloat16* __restrict__ Bb, int ldb, int K,
    __nv_bfloat16* As, __nv_bfloat16* Bs,
    float c[4][4][4], int wm, int wn, int gid, int tig, int tid)
{
    constexpr int RS = BK + 8;
    constexpr int SS = 128 * RS;
    constexpr int NSEG = BK / 8;
    int nk = K / BK;
    int lane = tid & 31;

    int a_row = ((lane >> 3) & 1) * 8 + (lane & 7);
    int a_col = (lane >> 4) * 8;
    int b_row = (lane >> 4) * 8 + (lane & 7);
    int b_col = ((lane >> 3) & 1) * 8;

    #pragma unroll
    for (int i = 0; i < NSEG / 2; i++) {
        int f = tid + i * 256;
        int row = f / NSEG, seg = (f % NSEG) * 8;
        cp16(&As[row * RS + seg], &Ab[(size_t)row * lda + seg]);
        cp16(&Bs[row * RS + seg], &Bb[(size_t)row * ldb + seg]);
    }
    asm volatile("cp.async.commit_group;");

    for (int i = 0; i < nk; i++) {
        if (i + 1 < nk) {
            int st = (i + 1) & 1, k0 = (i + 1) * BK;
            #pragma unroll
            for (int j = 0; j < NSEG / 2; j++) {
                int f = tid + j * 256;
                int row = f / NSEG, seg = (f % NSEG) * 8;
                cp16(&As[st * SS + row * RS + seg], &Ab[(size_t)row * lda + k0 + seg]);
                cp16(&Bs[st * SS + row * RS + seg], &Bb[(size_t)row * ldb + k0 + seg]);
            }
            asm volatile("cp.async.commit_group;");
            asm volatile("cp.async.wait_group 1;");
        } else {
            asm volatile("cp.async.wait_group 0;");
        }
        __syncthreads();
        int sb = (i & 1) * SS;
        #pragma unroll
        for (int kk = 0; kk < BK; kk += 16) {
            unsigned a[4][4], bfr[4][2];
            #pragma unroll
            for (int mi = 0; mi < 4; mi++)
                ldsm4(a[mi][0], a[mi][1], a[mi][2], a[mi][3],
                      &As[sb + (wm + mi * 16 + a_row) * RS + kk + a_col]);
            ldsm4(bfr[0][0], bfr[0][1], bfr[1][0], bfr[1][1],
                  &Bs[sb + (wn + b_row) * RS + kk + b_col]);
            ldsm4(bfr[2][0], bfr[2][1], bfr[3][0], bfr[3][1],
                  &Bs[sb + (wn + 16 + b_row) * RS + kk + b_col]);
            #pragma unroll
            for (int mi = 0; mi < 4; mi++)
                #pragma unroll
                for (int ni = 0; ni < 4; ni++)
                    asm volatile(
                        "mma.sync.aligned.m16n8k16.row.col.f32.bf16.bf16.f32 "
                        "{%0,%1,%2,%3}, {%4,%5,%6,%7}, {%8,%9}, {%0,%1,%2,%3};"
                        : "+f"(c[mi][ni][0]), "+f"(c[mi][ni][1]),
                          "+f"(c[mi][ni][2]), "+f"(c[mi][ni][3])
                        : "r"(a[mi][0]), "r"(a[mi][1]), "r"(a[mi][2]), "r"(a[mi][3]),
                          "r"(bfr[ni][0]), "r"(bfr[ni][1]));
        }
        __syncthreads();
    }
}

// =====================================================================
// 3c) merged qk + gate launch, LPT order: z==0 -> gate; z 1..12 -> qk by desc K
// =====================================================================
__global__ __launch_bounds__(256, 2) void gemm_qkgate(
    const __nv_bfloat16* __restrict__ coeffsb, const __nv_bfloat16* __restrict__ WfT,
    const float* __restrict__ biasf,
    __nv_bfloat16* __restrict__ Qb, __nv_bfloat16* __restrict__ Kb,
    const __nv_bfloat16* __restrict__ xb, const __nv_bfloat16* __restrict__ W1catT,
    const float* __restrict__ biasH, const float* __restrict__ W2,
    float* __restrict__ logits)
{
    __shared__ __nv_bfloat16 As[2 * 128 * 24];
    __shared__ __nv_bfloat16 Bs[2 * 128 * 24];
    int tid = threadIdx.x, warp = tid >> 5, lane = tid & 31;
    int wm = (warp >> 2) * 64, wn = (warp & 3) * 32;
    int gid = lane >> 2, tig = lane & 3;
    int z = blockIdx.z;
    int bm = blockIdx.y * 128;

    float c[4][4][4] = {};

    if (z > 0) {
        int idx = z - 1;
        int t = z_t[idx], s = z_s[idx];
        int off = c_off[s], len = c_len[s];
        int bn = blockIdx.x * 128;
        bf16_mainloop<16>(coeffsb + (size_t)bm * DIM + off, DIM,
                          WfT + (size_t)t * DIM * DIM + (size_t)bn * DIM + off, DIM,
                          len, As, Bs, c, wm, wn, gid, tig, tid);

        __nv_bfloat16* Cb = (t == 0 ? Qb : Kb) + s * DIM;
        const float* bias = biasf + (t * NS + s) * DIM;
        const int ldc = NS * DIM;
        #pragma unroll
        for (int mi = 0; mi < 4; mi++) {
            int r0 = bm + wm + mi * 16 + gid;
            #pragma unroll
            for (int ni = 0; ni < 4; ni++) {
                int col = bn + wn + ni * 8 + tig * 2;
                float b0 = bias[col], b1 = bias[col + 1];
                *(__nv_bfloat162*)&Cb[(size_t)r0 * ldc + col] =
                    __floats2bfloat162_rn(c[mi][ni][0] + b0, c[mi][ni][1] + b1);
                *(__nv_bfloat162*)&Cb[(size_t)(r0 + 8) * ldc + col] =
                    __floats2bfloat162_rn(c[mi][ni][2] + b0, c[mi][ni][3] + b1);
            }
        }
    } else {
        int r = blockIdx.x;
        int bn = r * 128;
        bf16_mainloop<16>(xb + (size_t)bm * DIM, DIM,
                          W1catT + (size_t)bn * DIM, DIM,
                          DIM, As, Bs, c, wm, wn, gid, tig, tid);

        float* partl = (float*)As;          // [4][128][6]
        float* w2s   = (float*)Bs;          // [128][6]
        for (int i = tid; i < 128 * 6; i += 256)
            w2s[i] = W2[r * (HIDN * NS) + i];
        __syncthreads();

        int warpcol = warp & 3;
        #pragma unroll
        for (int mi = 0; mi < 4; mi++) {
            #pragma unroll
            for (int rr = 0; rr < 2; rr++) {
                int row = wm + mi * 16 + gid + rr * 8;
                float p[6] = {};
                #pragma unroll
                for (int ni = 0; ni < 4; ni++) {
                    #pragma unroll
                    for (int l2 = 0; l2 < 2; l2++) {
                        int col = wn + ni * 8 + tig * 2 + l2;
                        float v = fmaxf(c[mi][ni][rr * 2 + l2] + biasH[bn + col], 0.f);
                        #pragma unroll
                        for (int s = 0; s < 6; s++)
                            p[s] += v * w2s[col * 6 + s];
                    }
                }
                #pragma unroll
                for (int o = 1; o <= 2; o <<= 1)
                    #pragma unroll
                    for (int s = 0; s < 6; s++)
                        p[s] += __shfl_xor_sync(0xffffffffu, p[s], o);
                if (tig == 0)
                    #pragma unroll
                    for (int s = 0; s < 6; s++)
                        partl[(warpcol * 128 + row) * 6 + s] = p[s];
            }
        }
        __syncthreads();
        for (int i = tid; i < 128 * 6; i += 256) {
            int row = i / 6, s = i % 6;
            float v = partl[(0 * 128 + row) * 6 + s] + partl[(1 * 128 + row) * 6 + s] +
                      partl[(2 * 128 + row) * 6 + s] + partl[(3 * 128 + row) * 6 + s];
            logits[(size_t)(bm + row) * (NREG * NS) + r * NS + s] = v;
        }
    }
}

// pre[:, h*128:(h+1)*128] = cs_h @ WfvT rows h*128.., K=544, BK=16 (2 CTA/SM)
__global__ __launch_bounds__(256, 2) void gemm_vpre_bf16(
    const __nv_bfloat16* __restrict__ csb, const __nv_bfloat16* __restrict__ WfvT,
    __nv_bfloat16* __restrict__ preb)
{
    __shared__ __nv_bfloat16 As[2 * 128 * 24];
    __shared__ __nv_bfloat16 Bs[2 * 128 * 24];
    int tid = threadIdx.x, warp = tid >> 5, lane = tid & 31;
    int wm = (warp >> 2) * 64, wn = (warp & 3) * 32;
    int gid = lane >> 2, tig = lane & 3;
    int h = blockIdx.z;
    int bm = blockIdx.y * 128;

    float c[4][4][4] = {};
    bf16_mainloop<16>(csb + (size_t)bm * (NHEAD * KEXT) + (size_t)h * KEXT, NHEAD * KEXT,
                      WfvT + (size_t)h * HD * KEXT, KEXT,
                      KEXT, As, Bs, c, wm, wn, gid, tig, tid);

    __nv_bfloat16* Cb = preb + h * HD;
    #pragma unroll
    for (int mi = 0; mi < 4; mi++) {
        int r0 = bm + wm + mi * 16 + gid;
        #pragma unroll
        for (int ni = 0; ni < 4; ni++) {
            int col = wn + ni * 8 + tig * 2;
            *(__nv_bfloat162*)&Cb[(size_t)r0 * DIM + col] =
                __floats2bfloat162_rn(c[mi][ni][0], c[mi][ni][1]);
            *(__nv_bfloat162*)&Cb[(size_t)(r0 + 8) * DIM + col] =
                __floats2bfloat162_rn(c[mi][ni][2], c[mi][ni][3]);
        }
    }
}

// agg = preb @ WoT + bo, fp32 out, BK=16 (2 CTA/SM)
__global__ __launch_bounds__(256, 2) void gemm_wo(
    const __nv_bfloat16* __restrict__ preb, const __nv_bfloat16* __restrict__ WoT,
    const float* __restrict__ bo, float* __restrict__ agg)
{
    __shared__ __nv_bfloat16 As[2 * 128 * 24];
    __shared__ __nv_bfloat16 Bs[2 * 128 * 24];
    int tid = threadIdx.x, warp = tid >> 5, lane = tid & 31;
    int wm = (warp >> 2) * 64, wn = (warp & 3) * 32;
    int gid = lane >> 2, tig = lane & 3;
    int bm = blockIdx.y * 128, bn = blockIdx.x * 128;

    float c[4][4][4] = {};
    bf16_mainloop<16>(preb + (size_t)bm * DIM, DIM,
                      WoT + (size_t)bn * DIM, DIM,
                      DIM, As, Bs, c, wm, wn, gid, tig, tid);

    #pragma unroll
    for (int mi = 0; mi < 4; mi++) {
        int r0 = bm + wm + mi * 16 + gid;
        #pragma unroll
        for (int ni = 0; ni < 4; ni++) {
            int col = bn + wn + ni * 8 + tig * 2;
            float b0 = bo[col], b1 = bo[col + 1];
            *(float2*)&agg[(size_t)r0 * DIM + col] =
                make_float2(c[mi][ni][0] + b0, c[mi][ni][1] + b1);
            *(float2*)&agg[(size_t)(r0 + 8) * DIM + col] =
                make_float2(c[mi][ni][2] + b0, c[mi][ni][3] + b1);
        }
    }
}

// =====================================================================
// 5) scores -> softmax -> gate softmax -> combine -> csb
// =====================================================================
__global__ __launch_bounds__(128) void score_kernel(
    const __nv_bfloat16* __restrict__ Qb, const __nv_bfloat16* __restrict__ Kb,
    const __nv_bfloat16* __restrict__ coeffsb,
    const int* __restrict__ labels, const float* __restrict__ logits,
    const float* __restrict__ b2,
    __nv_bfloat16* __restrict__ csb)
{
    int b = blockIdx.x;
    int h = threadIdx.x >> 5, lane = threadIdx.x & 31;
    int t = threadIdx.x;
    __shared__ __nv_bfloat16 sq[NS * DIM];
    __shared__ __nv_bfloat16 sk[NS * DIM];
    __shared__ float sco[DIM];
    __shared__ float wg[NS];
    __shared__ float att[NHEAD][NS][NS];
    __shared__ float ww[NHEAD][NS];

    const uint4* qs = (const uint4*)(Qb + (size_t)b * NS * DIM);
    const uint4* ks = (const uint4*)(Kb + (size_t)b * NS * DIM);
    uint4* qd = (uint4*)sq;
    uint4* kd = (uint4*)sk;
    #pragma unroll
    for (int i = 0; i < 3; i++) {
        qd[t + i * 128] = qs[t + i * 128];
        kd[t + i * 128] = ks[t + i * 128];
    }
    {
        const __nv_bfloat162* cb = (const __nv_bfloat162*)(coeffsb + (size_t)b * DIM);
        #pragma unroll
        for (int i = 0; i < 2; i++) {
            float2 f = __bfloat1622float2(cb[t * 2 + i]);
            sco[(t * 2 + i) * 2]     = f.x;
            sco[(t * 2 + i) * 2 + 1] = f.y;
        }
    }
    if (t == 0) {
        int r = labels[b];
        float li[NS], m = -1e30f;
        #pragma unroll
        for (int s = 0; s < NS; s++) {
            li[s] = logits[(size_t)b * (NREG * NS) + r * NS + s] + b2[r * NS + s];
            m = fmaxf(m, li[s]);
        }
        float sum = 0.f;
        #pragma unroll
        for (int s = 0; s < NS; s++) { li[s] = expf(li[s] - m); sum += li[s]; }
        float inv = 1.f / sum;
        #pragma unroll
        for (int s = 0; s < NS; s++) wg[s] = li[s] * inv;
    }
    __syncthreads();

    const __nv_bfloat162* q2 = (const __nv_bfloat162*)sq + h * 64;
    const __nv_bfloat162* k2 = (const __nv_bfloat162*)sk + h * 64;
    const float scale = 0.08838834764831845f;
    for (int p = lane; p < NS * NS; p += 32) {
        int i = p / NS, j = p % NS;
        const __nv_bfloat162* qi = q2 + i * 256;
        const __nv_bfloat162* kj = k2 + j * 256;
        float s0 = 0.f;
        #pragma unroll 16
        for (int d = 0; d < 64; d++) {
            float2 qa = __bfloat1622float2(qi[d]);
            float2 kb = __bfloat1622float2(kj[d]);
            s0 += qa.x * kb.x + qa.y * kb.y;
        }
        att[h][i][j] = s0 * scale;
    }
    __syncwarp();
    if (lane < NS) {
        int i = lane;
        float m = -1e30f;
        #pragma unroll
        for (int j = 0; j < NS; j++) m = fmaxf(m, att[h][i][j]);
        float e[NS], sum = 0.f;
        #pragma unroll
        for (int j = 0; j < NS; j++) { e[j] = expf(att[h][i][j] - m); sum += e[j]; }
        float inv = 1.f / sum;
        #pragma unroll
        for (int j = 0; j < NS; j++) att[h][i][j] = e[j] * inv;
    }
    __syncwarp();
    if (lane < NS) {
        int j = lane;
        float s = 0.f;
        #pragma unroll
        for (int i = 0; i < NS; i++) s += wg[i] * att[h][i][j];
        ww[h][j] = s;
    }
    __syncwarp();

    float wl[NS];
    #pragma unroll
    for (int j = 0; j < NS; j++) wl[j] = ww[h][j];

    __nv_bfloat16* crow = csb + ((size_t)b * NHEAD + h) * KEXT;
    #pragma unroll
    for (int kk = 0; kk < 16; kk++) {
        int k = kk * 32 + lane;
        int sl = (k < 16) ? 0 : (k < 32) ? 1 : (k < 64) ? 2 :
                 (k < 128) ? 3 : (k < 256) ? 4 : 5;
        crow[k] = __float2bfloat16(wl[sl] * sco[k]);
    }
    crow[512 + lane] = __float2bfloat16((lane < NS) ? wl[lane] : 0.f);
}

// =====================================================================
// 6) residual + layernorm: warp-per-row, 8 rows/block
// =====================================================================
__global__ __launch_bounds__(256) void ln_kernel(
    const float* __restrict__ x, const float* __restrict__ agg,
    const float* __restrict__ g, const float* __restrict__ be,
    float* __restrict__ out)
{
    int warp = threadIdx.x >> 5, lane = threadIdx.x & 31;
    int b = blockIdx.x * 8 + warp;
    size_t base = (size_t)b * DIM;
    const float4* x4 = (const float4*)(x + base);
    const float4* a4 = (const float4*)(agg + base);
    float4 y[4];
    float s = 0.f, q = 0.f;
    #pragma unroll
    for (int i = 0; i < 4; i++) {
        float4 xv = x4[lane + i * 32];
        float4 av = a4[lane + i * 32];
        y[i].x = xv.x + av.x; y[i].y = xv.y + av.y;
        y[i].z = xv.z + av.z; y[i].w = xv.w + av.w;
        s += y[i].x + y[i].y + y[i].z + y[i].w;
        q += y[i].x * y[i].x + y[i].y * y[i].y + y[i].z * y[i].z + y[i].w * y[i].w;
    }
    #pragma unroll
    for (int o = 16; o > 0; o >>= 1) {
        s += __shfl_xor_sync(0xffffffffu, s, o);
        q += __shfl_xor_sync(0xffffffffu, q, o);
    }
    float mu  = s * (1.f / DIM);
    float var = q * (1.f / DIM) - mu * mu;
    float rstd = rsqrtf(var + 1e-5f);
    const float4* g4 = (const float4*)g;
    const float4* b4 = (const float4*)be;
    float4* o4 = (float4*)(out + base);
    #pragma unroll
    for (int i = 0; i < 4; i++) {
        int idx = lane + i * 32;
        float4 gv = g4[idx], bv = b4[idx], r;
        r.x = (y[i].x - mu) * rstd * gv.x + bv.x;
        r.y = (y[i].y - mu) * rstd * gv.y + bv.y;
        r.z = (y[i].z - mu) * rstd * gv.z + bv.z;
        r.w = (y[i].w - mu) * rstd * gv.w + bv.w;
        o4[idx] = r;
    }
}

// =====================================================================
// host
// =====================================================================
extern "C" void kernel_launch(void* const* d_in, const int* in_sizes, int n_in,
                              void* d_out, int out_size)
{
    bool ins = (in_sizes[0] == BATCH * DIM);
    auto P = [&](int i_ins, int i_alpha) -> const float* {
        return (const float*)d_in[ins ? i_ins : i_alpha];
    };
    const float* x   = P(0, 17);
    const float* W1  = P(1, 0);
    const float* b1  = P(2, 7);
    const float* W2  = P(3, 1);
    const float* b2  = P(4, 8);
    const float* Wp  = P(5, 4);
    const float* bp  = P(6, 11);
    const float* Wq  = P(7, 5);  const float* bq = P(8, 12);
    const float* Wk  = P(9, 2);  const float* bk = P(10, 9);
    const float* Wv  = P(11, 6); const float* bv = P(12, 13);
    const float* Wo  = P(13, 3); const float* bo = P(14, 10);
    const float* lng = P(15, 15);
    const float* lnb = P(16, 14);
    const int* labels = (const int*)d_in[ins ? 17 : 16];
    float* out = (float*)d_out;

    float *logits, *W1cat, *biasH, *Apack, *WfE, *biasf, *agg;
    __nv_bfloat16 *coeffsb, *xb, *WfT, *W1catT, *WfvT, *WoT, *Qb, *Kb, *csb, *preb;
    cudaGetSymbolAddress((void**)&coeffsb, g_coeffsb);
    cudaGetSymbolAddress((void**)&xb,      g_xb);
    cudaGetSymbolAddress((void**)&logits,  g_logits);
    cudaGetSymbolAddress((void**)&W1cat,   g_W1cat);
    cudaGetSymbolAddress((void**)&biasH,   g_biasH);
    cudaGetSymbolAddress((void**)&Apack,   g_Apack);
    cudaGetSymbolAddress((void**)&WfE,     g_WfE);
    cudaGetSymbolAddress((void**)&biasf,   g_biasf);
    cudaGetSymbolAddress((void**)&WfT,     g_WfT);
    cudaGetSymbolAddress((void**)&W1catT,  g_W1catT);
    cudaGetSymbolAddress((void**)&WfvT,    g_WfvT);
    cudaGetSymbolAddress((void**)&WoT,     g_WoT);
    cudaGetSymbolAddress((void**)&Qb,      g_Qb);
    cudaGetSymbolAddress((void**)&Kb,      g_Kb);
    cudaGetSymbolAddress((void**)&csb,     g_csb);
    cudaGetSymbolAddress((void**)&preb,    g_preb);
    cudaGetSymbolAddress((void**)&agg,     g_agg);

    // 1. wavelet transform (warp-per-row) -> bf16 coeffs, bf16 x
    dwt_kernel<<<BATCH / 4, 128>>>(x, coeffsb, xb);

    // 2. weight prep
    prep_pack<<<MEXT, 512>>>(W1, b1, Wp, bp, W1cat, biasH, Apack);
    gemm_wf<<<dim3(4, 5, 3), 256>>>(Apack, Wq, Wk, Wv, WfE);
    transp_jobs<<<dim3(16, 17, 5), dim3(32, 8)>>>(WfE, W1cat, Wo, bq, bk, bv,
                                                  WfT, W1catT, WfvT, WoT, biasf);

    // 3+4. merged (LPT order): gate (z 0, K=512) then qk slices desc-K (z 1..12)
    gemm_qkgate<<<dim3(4, 64, 13), 256>>>(coeffsb, WfT, biasf, Qb, Kb,
                                          xb, W1catT, biasH, W2, logits);

    // 5. scores + both softmaxes + combine -> csb
    score_kernel<<<BATCH, 128>>>(Qb, Kb, coeffsb, labels, logits, b2, csb);

    // 6. pre = cs_h @ Wfv_ext (K=544, BK=16, single wave)
    gemm_vpre_bf16<<<dim3(1, 64, 4), 256>>>(csb, WfvT, preb);

    // 7. output projection + residual + layernorm
    gemm_wo<<<dim3(4, 64), 256>>>(preb, WoT, bo, agg);
    ln_kernel<<<BATCH / 8, 256>>>(x, agg, lng, lnb, out);
}

// round 17
// speedup vs baseline: 1.0283x; 1.0283x over previous
#include <cuda_runtime.h>
#include <cuda_bf16.h>
#include <math.h>

#define BATCH 8192
#define DIM   512
#define NREG  4
#define NS    6
#define HIDN  128
#define NHEAD 4
#define HD    128
#define KEXT  544                 // 512 coeffs + 6 ww + 26 pad (32-divisible)
#define MEXT  640                 // Apack rows: 512 Wp + 6 bp + 122 pad

// db8 lowpass (pywt 'periodization')
__constant__ float c_lo[16] = {
    -0.00011747678400228192f, 0.0006754494059985568f, -0.0003917403729959771f,
    -0.00487035299301066f,    0.008746094047015655f,  0.013981027917015516f,
    -0.04408825393106472f,    -0.01736930100202211f,  0.128747426620186f,
    0.00047248457399797254f,  -0.2840155429624281f,   -0.015829105256023893f,
    0.5853546836548691f,      0.6756307362980128f,    0.3128715909144659f,
    0.05441584224308161f
};

__constant__ int c_off[NS] = {0, 16, 32, 64, 128, 256};
__constant__ int c_len[NS] = {16, 16, 32, 64, 128, 256};
// LPT order for qk z-slices (descending K): (t, s) pairs
__constant__ int z_t[12] = {0, 1, 0, 1, 0, 1, 0, 1, 0, 1, 0, 1};
__constant__ int z_s[12] = {5, 5, 4, 4, 3, 3, 2, 2, 1, 1, 0, 0};

// ---- scratch ----
__device__ __nv_bfloat16 g_coeffsb[BATCH * DIM];
__device__ __nv_bfloat16 g_xb[BATCH * DIM];
__device__ float g_logits[BATCH * NREG * NS];
__device__ float g_W1cat[DIM * DIM];
__device__ float g_biasH[DIM];
__device__ float g_Apack[MEXT * DIM];
__device__ float g_WfE[3 * MEXT * DIM];
__device__ float g_biasf[2 * NS * DIM];
__device__ __nv_bfloat16 g_WfT[2 * DIM * DIM];
__device__ __nv_bfloat16 g_W1catT[DIM * DIM];
__device__ __nv_bfloat16 g_WfvT[DIM * KEXT];
__device__ __nv_bfloat16 g_WoT[DIM * DIM];
__device__ __nv_bfloat16 g_Qb[BATCH * NS * DIM];
__device__ __nv_bfloat16 g_Kb[BATCH * NS * DIM];
__device__ __nv_bfloat16 g_csb[(size_t)BATCH * NHEAD * KEXT];
__device__ __nv_bfloat16 g_preb[BATCH * DIM];
__device__ float g_agg[BATCH * DIM];

// =====================================================================
// 1) DWT: warp-per-row
// =====================================================================
__global__ __launch_bounds__(128) void dwt_kernel(
    const float* __restrict__ x,
    __nv_bfloat16* __restrict__ coeffsb,
    __nv_bfloat16* __restrict__ xb)
{
    __shared__ float sbuf[4][768];
    int w = threadIdx.x >> 5, lane = threadIdx.x & 31;
    int b = blockIdx.x * 4 + w;
    float* buf512 = sbuf[w];
    float* buf256 = sbuf[w] + 512;

    const float4* xr = (const float4*)(x + (size_t)b * DIM);
    __nv_bfloat162* xbw = (__nv_bfloat162*)(xb + (size_t)b * DIM);
    #pragma unroll
    for (int i = lane; i < 128; i += 32) {
        float4 v = xr[i];
        buf512[i * 4 + 0] = v.x;
        buf512[i * 4 + 1] = v.y;
        buf512[i * 4 + 2] = v.z;
        buf512[i * 4 + 3] = v.w;
        xbw[i * 2 + 0] = __floats2bfloat162_rn(v.x, v.y);
        xbw[i * 2 + 1] = __floats2bfloat162_rn(v.z, v.w);
    }
    __syncwarp();

    float* src = buf512;
    float* dst = buf256;
    int n = DIM;
    for (int lev = 0; lev < 5; lev++) {
        int nh = n >> 1;
        for (int k = lane; k < nh; k += 32) {
            float sa = 0.f, sd = 0.f;
            #pragma unroll
            for (int j = 0; j < 16; j++) {
                int m = 2 * k + 1 - j;
                if (m < 0) m += n;
                float av = src[m];
                float hj = c_lo[15 - j] * ((j & 1) ? 1.f : -1.f);
                sa += c_lo[j] * av;
                sd += hj * av;
            }
            dst[k] = sa;
            coeffsb[(size_t)b * DIM + nh + k] = __float2bfloat16(sd);
        }
        __syncwarp();
        float* t = src; src = dst; dst = t;
        n = nh;
    }
    for (int k = lane; k < 16; k += 32)
        coeffsb[(size_t)b * DIM + k] = __float2bfloat16(src[k]);
}

// =====================================================================
// 2) weight repacking
// =====================================================================
__global__ void prep_pack(const float* __restrict__ W1, const float* __restrict__ b1,
                          const float* __restrict__ Wp, const float* __restrict__ bp,
                          float* __restrict__ W1cat, float* __restrict__ biasH,
                          float* __restrict__ Apack)
{
    int row = blockIdx.x;
    int c   = threadIdx.x;
    int r = c >> 7, j = c & 127;

    float av;
    if (row < 512) {
        W1cat[row * DIM + c] = W1[r * (516 * 128) + row * 128 + j];
        int s, k;
        if      (row < 16)  { s = 0; k = row;       }
        else if (row < 32)  { s = 1; k = row - 16;  }
        else if (row < 64)  { s = 2; k = row - 32;  }
        else if (row < 128) { s = 3; k = row - 64;  }
        else if (row < 256) { s = 4; k = row - 128; }
        else                { s = 5; k = row - 256; }
        av = Wp[s * (DIM * DIM) + k * DIM + c];
        if (row == 0)
            biasH[c] = b1[r * 128 + j] + W1[r * (516 * 128) + (512 + r) * 128 + j];
    } else if (row < 518) {
        av = bp[(row - 512) * DIM + c];
    } else {
        av = 0.f;
    }
    Apack[row * DIM + c] = av;
}

// tiled transpose + bf16 (5 jobs) + bias finishing lane (blockIdx.y == 16)
__global__ void transp_jobs(const float* __restrict__ WfE, const float* __restrict__ W1cat,
                            const float* __restrict__ Wo,
                            const float* __restrict__ bq, const float* __restrict__ bk,
                            const float* __restrict__ bv,
                            __nv_bfloat16* __restrict__ WfT,
                            __nv_bfloat16* __restrict__ W1catT,
                            __nv_bfloat16* __restrict__ WfvT,
                            __nv_bfloat16* __restrict__ WoT,
                            float* __restrict__ biasf)
{
    int job = blockIdx.z;
    if (blockIdx.y == 16) {
        int d = blockIdx.x * 32 + threadIdx.x;
        if (job == 0 || job == 1) {
            const float* bvec = (job == 0) ? bq : bk;
            for (int s = threadIdx.y; s < NS; s += 8)
                biasf[(job * NS + s) * DIM + d] =
                    WfE[(size_t)job * MEXT * DIM + (size_t)(512 + s) * DIM + d] + bvec[d];
        } else if (job == 3) {
            for (int i = threadIdx.y; i < 32; i += 8) {
                float v = 0.f;
                if (i < NS)
                    v = WfE[(size_t)2 * MEXT * DIM + (size_t)(512 + i) * DIM + d] + bv[d];
                WfvT[(size_t)d * KEXT + 512 + i] = __float2bfloat16(v);
            }
        }
        return;
    }

    const float* src;
    __nv_bfloat16* dst;
    int dstStride = DIM;
    switch (job) {
        case 0: src = WfE;                    dst = WfT;             break;
        case 1: src = WfE + MEXT * DIM;       dst = WfT + DIM * DIM; break;
        case 2: src = W1cat;                  dst = W1catT;          break;
        case 3: src = WfE + 2 * MEXT * DIM;   dst = WfvT; dstStride = KEXT; break;
        default: src = Wo;                    dst = WoT;             break;
    }
    __shared__ float tile[32][33];
    int k0 = blockIdx.y * 32, n0 = blockIdx.x * 32;
    for (int i = threadIdx.y; i < 32; i += 8)
        tile[i][threadIdx.x] = src[(size_t)(k0 + i) * DIM + n0 + threadIdx.x];
    __syncthreads();
    for (int i = threadIdx.y; i < 32; i += 8)
        dst[(size_t)(n0 + i) * dstStride + k0 + threadIdx.x] =
            __float2bfloat16(tile[threadIdx.x][i]);
}

// =====================================================================
// 3) tf32 GEMM (Wf prep only)
// =====================================================================
__device__ __forceinline__ void cp16(void* dst, const void* src) {
    unsigned d = (unsigned)__cvta_generic_to_shared(dst);
    asm volatile("cp.async.ca.shared.global [%0], [%1], 16;" :: "r"(d), "l"(src));
}

__device__ __forceinline__ void ldsm4(unsigned& r0, unsigned& r1,
                                      unsigned& r2, unsigned& r3, const void* p) {
    unsigned a = (unsigned)__cvta_generic_to_shared(p);
    asm volatile("ldmatrix.sync.aligned.m8n8.x4.shared.b16 {%0,%1,%2,%3}, [%4];"
                 : "=r"(r0), "=r"(r1), "=r"(r2), "=r"(r3) : "r"(a));
}

__device__ __forceinline__ void gemm_tile(
    const float* __restrict__ A, int lda,
    const float* __restrict__ B, int ldb,
    float* __restrict__ C, int ldc, int K,
    int bm, int bn)
{
    __shared__ float As[2][128][20];
    __shared__ float Bs[2][16][136];
    int t = threadIdx.x;
    int warp = t >> 5, lane = t & 31;
    int wm = (warp >> 2) * 64;
    int wn = (warp & 3) * 32;
    int gid = lane >> 2, tig = lane & 3;

    int aRow = t >> 2, aC = (t & 3) << 2;
    int bRow = t >> 5, bC = (t & 31) << 2;
    const float* Ab = A + (size_t)bm * lda;
    int nk = K >> 4;

    cp16(&As[0][aRow][aC],      &Ab[(size_t)aRow * lda + aC]);
    cp16(&As[0][aRow + 64][aC], &Ab[(size_t)(aRow + 64) * lda + aC]);
    cp16(&Bs[0][bRow][bC],      &B[(size_t)bRow * ldb + bn + bC]);
    cp16(&Bs[0][bRow + 8][bC],  &B[(size_t)(bRow + 8) * ldb + bn + bC]);
    asm volatile("cp.async.commit_group;");

    float c[4][4][4] = {};

    for (int i = 0; i < nk; i++) {
        if (i + 1 < nk) {
            int st = (i + 1) & 1, k0 = (i + 1) << 4;
            cp16(&As[st][aRow][aC],      &Ab[(size_t)aRow * lda + k0 + aC]);
            cp16(&As[st][aRow + 64][aC], &Ab[(size_t)(aRow + 64) * lda + k0 + aC]);
            cp16(&Bs[st][bRow][bC],      &B[(size_t)(k0 + bRow) * ldb + bn + bC]);
            cp16(&Bs[st][bRow + 8][bC],  &B[(size_t)(k0 + bRow + 8) * ldb + bn + bC]);
            asm volatile("cp.async.commit_group;");
            asm volatile("cp.async.wait_group 1;");
        } else {
            asm volatile("cp.async.wait_group 0;");
        }
        __syncthreads();
        int st = i & 1;
        #pragma unroll
        for (int kk = 0; kk < 16; kk += 8) {
            unsigned a[4][4], b[4][2];
            #pragma unroll
            for (int mi = 0; mi < 4; mi++) {
                const float* p = &As[st][wm + mi * 16 + gid][kk + tig];
                a[mi][0] = __float_as_uint(p[0]);
                a[mi][1] = __float_as_uint(p[8 * 20]);
                a[mi][2] = __float_as_uint(p[4]);
                a[mi][3] = __float_as_uint(p[8 * 20 + 4]);
            }
            #pragma unroll
            for (int ni = 0; ni < 4; ni++) {
                const float* p = &Bs[st][kk + tig][wn + ni * 8 + gid];
                b[ni][0] = __float_as_uint(p[0]);
                b[ni][1] = __float_as_uint(p[4 * 136]);
            }
            #pragma unroll
            for (int mi = 0; mi < 4; mi++)
                #pragma unroll
                for (int ni = 0; ni < 4; ni++)
                    asm volatile(
                        "mma.sync.aligned.m16n8k8.row.col.f32.tf32.tf32.f32 "
                        "{%0,%1,%2,%3}, {%4,%5,%6,%7}, {%8,%9}, {%0,%1,%2,%3};"
                        : "+f"(c[mi][ni][0]), "+f"(c[mi][ni][1]),
                          "+f"(c[mi][ni][2]), "+f"(c[mi][ni][3])
                        : "r"(a[mi][0]), "r"(a[mi][1]), "r"(a[mi][2]), "r"(a[mi][3]),
                          "r"(b[ni][0]), "r"(b[ni][1]));
        }
        __syncthreads();
    }

    #pragma unroll
    for (int mi = 0; mi < 4; mi++) {
        int r0 = bm + wm + mi * 16 + gid;
        #pragma unroll
        for (int ni = 0; ni < 4; ni++) {
            int col = bn + wn + ni * 8 + tig * 2;
            *(float2*)&C[(size_t)r0 * ldc + col] =
                make_float2(c[mi][ni][0], c[mi][ni][1]);
            *(float2*)&C[(size_t)(r0 + 8) * ldc + col] =
                make_float2(c[mi][ni][2], c[mi][ni][3]);
        }
    }
}

__global__ __launch_bounds__(256, 2) void gemm_wf(
    const float* __restrict__ Apack,
    const float* __restrict__ Wq, const float* __restrict__ Wk,
    const float* __restrict__ Wv, float* __restrict__ WfE)
{
    int z = blockIdx.z;
    const float* B = (z == 0) ? Wq : (z == 1) ? Wk : Wv;
    float* C = WfE + (size_t)z * MEXT * DIM;
    gemm_tile(Apack, DIM, B, DIM, C, DIM, DIM,
              blockIdx.y * 128, blockIdx.x * 128);
}

// =====================================================================
// 3b) bf16 GEMM mainloop template
// =====================================================================
template<int BK>
__device__ __forceinline__ void bf16_mainloop(
    const __nv_bfloat16* __restrict__ Ab, int lda,
    const __nv_bfloat16* __restrict__ Bb, int ldb, int K,
    __nv_bfloat16* As, __nv_bfloat16* Bs,
    float c[4][4][4], int wm, int wn, int gid, int tig, int tid)
{
    constexpr int RS = BK + 8;
    constexpr int SS = 128 * RS;
    constexpr int NSEG = BK / 8;
    int nk = K / BK;
    int lane = tid & 31;

    int a_row = ((lane >> 3) & 1) * 8 + (lane & 7);
    int a_col = (lane >> 4) * 8;
    int b_row = (lane >> 4) * 8 + (lane & 7);
    int b_col = ((lane >> 3) & 1) * 8;

    #pragma unroll
    for (int i = 0; i < NSEG / 2; i++) {
        int f = tid + i * 256;
        int row = f / NSEG, seg = (f % NSEG) * 8;
        cp16(&As[row * RS + seg], &Ab[(size_t)row * lda + seg]);
        cp16(&Bs[row * RS + seg], &Bb[(size_t)row * ldb + seg]);
    }
    asm volatile("cp.async.commit_group;");

    for (int i = 0; i < nk; i++) {
        if (i + 1 < nk) {
            int st = (i + 1) & 1, k0 = (i + 1) * BK;
            #pragma unroll
            for (int j = 0; j < NSEG / 2; j++) {
                int f = tid + j * 256;
                int row = f / NSEG, seg = (f % NSEG) * 8;
                cp16(&As[st * SS + row * RS + seg], &Ab[(size_t)row * lda + k0 + seg]);
                cp16(&Bs[st * SS + row * RS + seg], &Bb[(size_t)row * ldb + k0 + seg]);
            }
            asm volatile("cp.async.commit_group;");
            asm volatile("cp.async.wait_group 1;");
        } else {
            asm volatile("cp.async.wait_group 0;");
        }
        __syncthreads();
        int sb = (i & 1) * SS;
        #pragma unroll
        for (int kk = 0; kk < BK; kk += 16) {
            unsigned a[4][4], bfr[4][2];
            #pragma unroll
            for (int mi = 0; mi < 4; mi++)
                ldsm4(a[mi][0], a[mi][1], a[mi][2], a[mi][3],
                      &As[sb + (wm + mi * 16 + a_row) * RS + kk + a_col]);
            ldsm4(bfr[0][0], bfr[0][1], bfr[1][0], bfr[1][1],
                  &Bs[sb + (wn + b_row) * RS + kk + b_col]);
            ldsm4(bfr[2][0], bfr[2][1], bfr[3][0], bfr[3][1],
                  &Bs[sb + (wn + 16 + b_row) * RS + kk + b_col]);
            #pragma unroll
            for (int mi = 0; mi < 4; mi++)
                #pragma unroll
                for (int ni = 0; ni < 4; ni++)
                    asm volatile(
                        "mma.sync.aligned.m16n8k16.row.col.f32.bf16.bf16.f32 "
                        "{%0,%1,%2,%3}, {%4,%5,%6,%7}, {%8,%9}, {%0,%1,%2,%3};"
                        : "+f"(c[mi][ni][0]), "+f"(c[mi][ni][1]),
                          "+f"(c[mi][ni][2]), "+f"(c[mi][ni][3])
                        : "r"(a[mi][0]), "r"(a[mi][1]), "r"(a[mi][2]), "r"(a[mi][3]),
                          "r"(bfr[ni][0]), "r"(bfr[ni][1]));
        }
        __syncthreads();
    }
}

// =====================================================================
// 3c) merged qk + gate launch, LPT order: z==0 -> gate; z 1..12 -> qk by desc K
// =====================================================================
__global__ __launch_bounds__(256, 2) void gemm_qkgate(
    const __nv_bfloat16* __restrict__ coeffsb, const __nv_bfloat16* __restrict__ WfT,
    const float* __restrict__ biasf,
    __nv_bfloat16* __restrict__ Qb, __nv_bfloat16* __restrict__ Kb,
    const __nv_bfloat16* __restrict__ xb, const __nv_bfloat16* __restrict__ W1catT,
    const float* __restrict__ biasH, const float* __restrict__ W2,
    float* __restrict__ logits)
{
    __shared__ __nv_bfloat16 As[2 * 128 * 24];
    __shared__ __nv_bfloat16 Bs[2 * 128 * 24];
    int tid = threadIdx.x, warp = tid >> 5, lane = tid & 31;
    int wm = (warp >> 2) * 64, wn = (warp & 3) * 32;
    int gid = lane >> 2, tig = lane & 3;
    int z = blockIdx.z;
    int bm = blockIdx.y * 128;

    float c[4][4][4] = {};

    if (z > 0) {
        int idx = z - 1;
        int t = z_t[idx], s = z_s[idx];
        int off = c_off[s], len = c_len[s];
        int bn = blockIdx.x * 128;
        bf16_mainloop<16>(coeffsb + (size_t)bm * DIM + off, DIM,
                          WfT + (size_t)t * DIM * DIM + (size_t)bn * DIM + off, DIM,
                          len, As, Bs, c, wm, wn, gid, tig, tid);

        __nv_bfloat16* Cb = (t == 0 ? Qb : Kb) + s * DIM;
        const float* bias = biasf + (t * NS + s) * DIM;
        const int ldc = NS * DIM;
        #pragma unroll
        for (int mi = 0; mi < 4; mi++) {
            int r0 = bm + wm + mi * 16 + gid;
            #pragma unroll
            for (int ni = 0; ni < 4; ni++) {
                int col = bn + wn + ni * 8 + tig * 2;
                float b0 = bias[col], b1 = bias[col + 1];
                *(__nv_bfloat162*)&Cb[(size_t)r0 * ldc + col] =
                    __floats2bfloat162_rn(c[mi][ni][0] + b0, c[mi][ni][1] + b1);
                *(__nv_bfloat162*)&Cb[(size_t)(r0 + 8) * ldc + col] =
                    __floats2bfloat162_rn(c[mi][ni][2] + b0, c[mi][ni][3] + b1);
            }
        }
    } else {
        int r = blockIdx.x;
        int bn = r * 128;
        bf16_mainloop<16>(xb + (size_t)bm * DIM, DIM,
                          W1catT + (size_t)bn * DIM, DIM,
                          DIM, As, Bs, c, wm, wn, gid, tig, tid);

        float* partl = (float*)As;          // [4][128][6]
        float* w2s   = (float*)Bs;          // [128][6]
        for (int i = tid; i < 128 * 6; i += 256)
            w2s[i] = W2[r * (HIDN * NS) + i];
        __syncthreads();

        int warpcol = warp & 3;
        #pragma unroll
        for (int mi = 0; mi < 4; mi++) {
            #pragma unroll
            for (int rr = 0; rr < 2; rr++) {
                int row = wm + mi * 16 + gid + rr * 8;
                float p[6] = {};
                #pragma unroll
                for (int ni = 0; ni < 4; ni++) {
                    #pragma unroll
                    for (int l2 = 0; l2 < 2; l2++) {
                        int col = wn + ni * 8 + tig * 2 + l2;
                        float v = fmaxf(c[mi][ni][rr * 2 + l2] + biasH[bn + col], 0.f);
                        #pragma unroll
                        for (int s = 0; s < 6; s++)
                            p[s] += v * w2s[col * 6 + s];
                    }
                }
                #pragma unroll
                for (int o = 1; o <= 2; o <<= 1)
                    #pragma unroll
                    for (int s = 0; s < 6; s++)
                        p[s] += __shfl_xor_sync(0xffffffffu, p[s], o);
                if (tig == 0)
                    #pragma unroll
                    for (int s = 0; s < 6; s++)
                        partl[(warpcol * 128 + row) * 6 + s] = p[s];
            }
        }
        __syncthreads();
        for (int i = tid; i < 128 * 6; i += 256) {
            int row = i / 6, s = i % 6;
            float v = partl[(0 * 128 + row) * 6 + s] + partl[(1 * 128 + row) * 6 + s] +
                      partl[(2 * 128 + row) * 6 + s] + partl[(3 * 128 + row) * 6 + s];
            logits[(size_t)(bm + row) * (NREG * NS) + r * NS + s] = v;
        }
    }
}

// pre[:, h*128:(h+1)*128] = cs_h @ WfvT rows h*128.., K=544, BK=32
__global__ __launch_bounds__(256, 2) void gemm_vpre_bf16(
    const __nv_bfloat16* __restrict__ csb, const __nv_bfloat16* __restrict__ WfvT,
    __nv_bfloat16* __restrict__ preb)
{
    __shared__ __nv_bfloat16 As[2 * 128 * 40];
    __shared__ __nv_bfloat16 Bs[2 * 128 * 40];
    int tid = threadIdx.x, warp = tid >> 5, lane = tid & 31;
    int wm = (warp >> 2) * 64, wn = (warp & 3) * 32;
    int gid = lane >> 2, tig = lane & 3;
    int h = blockIdx.z;
    int bm = blockIdx.y * 128;

    float c[4][4][4] = {};
    bf16_mainloop<32>(csb + (size_t)bm * (NHEAD * KEXT) + (size_t)h * KEXT, NHEAD * KEXT,
                      WfvT + (size_t)h * HD * KEXT, KEXT,
                      KEXT, As, Bs, c, wm, wn, gid, tig, tid);

    __nv_bfloat16* Cb = preb + h * HD;
    #pragma unroll
    for (int mi = 0; mi < 4; mi++) {
        int r0 = bm + wm + mi * 16 + gid;
        #pragma unroll
        for (int ni = 0; ni < 4; ni++) {
            int col = wn + ni * 8 + tig * 2;
            *(__nv_bfloat162*)&Cb[(size_t)r0 * DIM + col] =
                __floats2bfloat162_rn(c[mi][ni][0], c[mi][ni][1]);
            *(__nv_bfloat162*)&Cb[(size_t)(r0 + 8) * DIM + col] =
                __floats2bfloat162_rn(c[mi][ni][2], c[mi][ni][3]);
        }
    }
}

// agg = preb @ WoT + bo, fp32 out, BK=32
__global__ __launch_bounds__(256, 2) void gemm_wo(
    const __nv_bfloat16* __restrict__ preb, const __nv_bfloat16* __restrict__ WoT,
    const float* __restrict__ bo, float* __restrict__ agg)
{
    __shared__ __nv_bfloat16 As[2 * 128 * 40];
    __shared__ __nv_bfloat16 Bs[2 * 128 * 40];
    int tid = threadIdx.x, warp = tid >> 5, lane = tid & 31;
    int wm = (warp >> 2) * 64, wn = (warp & 3) * 32;
    int gid = lane >> 2, tig = lane & 3;
    int bm = blockIdx.y * 128, bn = blockIdx.x * 128;

    float c[4][4][4] = {};
    bf16_mainloop<32>(preb + (size_t)bm * DIM, DIM,
                      WoT + (size_t)bn * DIM, DIM,
                      DIM, As, Bs, c, wm, wn, gid, tig, tid);

    #pragma unroll
    for (int mi = 0; mi < 4; mi++) {
        int r0 = bm + wm + mi * 16 + gid;
        #pragma unroll
        for (int ni = 0; ni < 4; ni++) {
            int col = bn + wn + ni * 8 + tig * 2;
            float b0 = bo[col], b1 = bo[col + 1];
            *(float2*)&agg[(size_t)r0 * DIM + col] =
                make_float2(c[mi][ni][0] + b0, c[mi][ni][1] + b1);
            *(float2*)&agg[(size_t)(r0 + 8) * DIM + col] =
                make_float2(c[mi][ni][2] + b0, c[mi][ni][3] + b1);
        }
    }
}

// =====================================================================
// 5) scores -> softmax -> gate softmax -> combine -> csb
// =====================================================================
__global__ __launch_bounds__(128) void score_kernel(
    const __nv_bfloat16* __restrict__ Qb, const __nv_bfloat16* __restrict__ Kb,
    const __nv_bfloat16* __restrict__ coeffsb,
    const int* __restrict__ labels, const float* __restrict__ logits,
    const float* __restrict__ b2,
    __nv_bfloat16* __restrict__ csb)
{
    int b = blockIdx.x;
    int h = threadIdx.x >> 5, lane = threadIdx.x & 31;
    int t = threadIdx.x;
    __shared__ __nv_bfloat16 sq[NS * DIM];
    __shared__ __nv_bfloat16 sk[NS * DIM];
    __shared__ float sco[DIM];
    __shared__ float wg[NS];
    __shared__ float att[NHEAD][NS][NS];
    __shared__ float ww[NHEAD][NS];

    const uint4* qs = (const uint4*)(Qb + (size_t)b * NS * DIM);
    const uint4* ks = (const uint4*)(Kb + (size_t)b * NS * DIM);
    uint4* qd = (uint4*)sq;
    uint4* kd = (uint4*)sk;
    #pragma unroll
    for (int i = 0; i < 3; i++) {
        qd[t + i * 128] = qs[t + i * 128];
        kd[t + i * 128] = ks[t + i * 128];
    }
    {
        const __nv_bfloat162* cb = (const __nv_bfloat162*)(coeffsb + (size_t)b * DIM);
        #pragma unroll
        for (int i = 0; i < 2; i++) {
            float2 f = __bfloat1622float2(cb[t * 2 + i]);
            sco[(t * 2 + i) * 2]     = f.x;
            sco[(t * 2 + i) * 2 + 1] = f.y;
        }
    }
    if (t == 0) {
        int r = labels[b];
        float li[NS], m = -1e30f;
        #pragma unroll
        for (int s = 0; s < NS; s++) {
            li[s] = logits[(size_t)b * (NREG * NS) + r * NS + s] + b2[r * NS + s];
            m = fmaxf(m, li[s]);
        }
        float sum = 0.f;
        #pragma unroll
        for (int s = 0; s < NS; s++) { li[s] = expf(li[s] - m); sum += li[s]; }
        float inv = 1.f / sum;
        #pragma unroll
        for (int s = 0; s < NS; s++) wg[s] = li[s] * inv;
    }
    __syncthreads();

    const __nv_bfloat162* q2 = (const __nv_bfloat162*)sq + h * 64;
    const __nv_bfloat162* k2 = (const __nv_bfloat162*)sk + h * 64;
    const float scale = 0.08838834764831845f;
    for (int p = lane; p < NS * NS; p += 32) {
        int i = p / NS, j = p % NS;
        const __nv_bfloat162* qi = q2 + i * 256;
        const __nv_bfloat162* kj = k2 + j * 256;
        float s0 = 0.f;
        #pragma unroll 16
        for (int d = 0; d < 64; d++) {
            float2 qa = __bfloat1622float2(qi[d]);
            float2 kb = __bfloat1622float2(kj[d]);
            s0 += qa.x * kb.x + qa.y * kb.y;
        }
        att[h][i][j] = s0 * scale;
    }
    __syncwarp();
    if (lane < NS) {
        int i = lane;
        float m = -1e30f;
        #pragma unroll
        for (int j = 0; j < NS; j++) m = fmaxf(m, att[h][i][j]);
        float e[NS], sum = 0.f;
        #pragma unroll
        for (int j = 0; j < NS; j++) { e[j] = expf(att[h][i][j] - m); sum += e[j]; }
        float inv = 1.f / sum;
        #pragma unroll
        for (int j = 0; j < NS; j++) att[h][i][j] = e[j] * inv;
    }
    __syncwarp();
    if (lane < NS) {
        int j = lane;
        float s = 0.f;
        #pragma unroll
        for (int i = 0; i < NS; i++) s += wg[i] * att[h][i][j];
        ww[h][j] = s;
    }
    __syncwarp();

    float wl[NS];
    #pragma unroll
    for (int j = 0; j < NS; j++) wl[j] = ww[h][j];

    __nv_bfloat16* crow = csb + ((size_t)b * NHEAD + h) * KEXT;
    #pragma unroll
    for (int kk = 0; kk < 16; kk++) {
        int k = kk * 32 + lane;
        int sl = (k < 16) ? 0 : (k < 32) ? 1 : (k < 64) ? 2 :
                 (k < 128) ? 3 : (k < 256) ? 4 : 5;
        crow[k] = __float2bfloat16(wl[sl] * sco[k]);
    }
    crow[512 + lane] = __float2bfloat16((lane < NS) ? wl[lane] : 0.f);
}

// =====================================================================
// 6) residual + layernorm: warp-per-row, 8 rows/block
// =====================================================================
__global__ __launch_bounds__(256) void ln_kernel(
    const float* __restrict__ x, const float* __restrict__ agg,
    const float* __restrict__ g, const float* __restrict__ be,
    float* __restrict__ out)
{
    int warp = threadIdx.x >> 5, lane = threadIdx.x & 31;
    int b = blockIdx.x * 8 + warp;
    size_t base = (size_t)b * DIM;
    const float4* x4 = (const float4*)(x + base);
    const float4* a4 = (const float4*)(agg + base);
    float4 y[4];
    float s = 0.f, q = 0.f;
    #pragma unroll
    for (int i = 0; i < 4; i++) {
        float4 xv = x4[lane + i * 32];
        float4 av = a4[lane + i * 32];
        y[i].x = xv.x + av.x; y[i].y = xv.y + av.y;
        y[i].z = xv.z + av.z; y[i].w = xv.w + av.w;
        s += y[i].x + y[i].y + y[i].z + y[i].w;
        q += y[i].x * y[i].x + y[i].y * y[i].y + y[i].z * y[i].z + y[i].w * y[i].w;
    }
    #pragma unroll
    for (int o = 16; o > 0; o >>= 1) {
        s += __shfl_xor_sync(0xffffffffu, s, o);
        q += __shfl_xor_sync(0xffffffffu, q, o);
    }
    float mu  = s * (1.f / DIM);
    float var = q * (1.f / DIM) - mu * mu;
    float rstd = rsqrtf(var + 1e-5f);
    const float4* g4 = (const float4*)g;
    const float4* b4 = (const float4*)be;
    float4* o4 = (float4*)(out + base);
    #pragma unroll
    for (int i = 0; i < 4; i++) {
        int idx = lane + i * 32;
        float4 gv = g4[idx], bv = b4[idx], r;
        r.x = (y[i].x - mu) * rstd * gv.x + bv.x;
        r.y = (y[i].y - mu) * rstd * gv.y + bv.y;
        r.z = (y[i].z - mu) * rstd * gv.z + bv.z;
        r.w = (y[i].w - mu) * rstd * gv.w + bv.w;
        o4[idx] = r;
    }
}

// =====================================================================
// host
// =====================================================================
extern "C" void kernel_launch(void* const* d_in, const int* in_sizes, int n_in,
                              void* d_out, int out_size)
{
    bool ins = (in_sizes[0] == BATCH * DIM);
    auto P = [&](int i_ins, int i_alpha) -> const float* {
        return (const float*)d_in[ins ? i_ins : i_alpha];
    };
    const float* x   = P(0, 17);
    const float* W1  = P(1, 0);
    const float* b1  = P(2, 7);
    const float* W2  = P(3, 1);
    const float* b2  = P(4, 8);
    const float* Wp  = P(5, 4);
    const float* bp  = P(6, 11);
    const float* Wq  = P(7, 5);  const float* bq = P(8, 12);
    const float* Wk  = P(9, 2);  const float* bk = P(10, 9);
    const float* Wv  = P(11, 6); const float* bv = P(12, 13);
    const float* Wo  = P(13, 3); const float* bo = P(14, 10);
    const float* lng = P(15, 15);
    const float* lnb = P(16, 14);
    const int* labels = (const int*)d_in[ins ? 17 : 16];
    float* out = (float*)d_out;

    float *logits, *W1cat, *biasH, *Apack, *WfE, *biasf, *agg;
    __nv_bfloat16 *coeffsb, *xb, *WfT, *W1catT, *WfvT, *WoT, *Qb, *Kb, *csb, *preb;
    cudaGetSymbolAddress((void**)&coeffsb, g_coeffsb);
    cudaGetSymbolAddress((void**)&xb,      g_xb);
    cudaGetSymbolAddress((void**)&logits,  g_logits);
    cudaGetSymbolAddress((void**)&W1cat,   g_W1cat);
    cudaGetSymbolAddress((void**)&biasH,   g_biasH);
    cudaGetSymbolAddress((void**)&Apack,   g_Apack);
    cudaGetSymbolAddress((void**)&WfE,     g_WfE);
    cudaGetSymbolAddress((void**)&biasf,   g_biasf);
    cudaGetSymbolAddress((void**)&WfT,     g_WfT);
    cudaGetSymbolAddress((void**)&W1catT,  g_W1catT);
    cudaGetSymbolAddress((void**)&WfvT,    g_WfvT);
    cudaGetSymbolAddress((void**)&WoT,     g_WoT);
    cudaGetSymbolAddress((void**)&Qb,      g_Qb);
    cudaGetSymbolAddress((void**)&Kb,      g_Kb);
    cudaGetSymbolAddress((void**)&csb,     g_csb);
    cudaGetSymbolAddress((void**)&preb,    g_preb);
    cudaGetSymbolAddress((void**)&agg,     g_agg);

    // 1. wavelet transform (warp-per-row) -> bf16 coeffs, bf16 x
    dwt_kernel<<<BATCH / 4, 128>>>(x, coeffsb, xb);

    // 2. weight prep
    prep_pack<<<MEXT, 512>>>(W1, b1, Wp, bp, W1cat, biasH, Apack);
    gemm_wf<<<dim3(4, 5, 3), 256>>>(Apack, Wq, Wk, Wv, WfE);
    transp_jobs<<<dim3(16, 17, 5), dim3(32, 8)>>>(WfE, W1cat, Wo, bq, bk, bv,
                                                  WfT, W1catT, WfvT, WoT, biasf);

    // 3+4. merged (LPT order): gate (z 0, K=512) then qk slices desc-K (z 1..12)
    gemm_qkgate<<<dim3(4, 64, 13), 256>>>(coeffsb, WfT, biasf, Qb, Kb,
                                          xb, W1catT, biasH, W2, logits);

    // 5. scores + both softmaxes + combine -> csb
    score_kernel<<<BATCH, 128>>>(Qb, Kb, coeffsb, labels, logits, b2, csb);

    // 6. pre = cs_h @ Wfv_ext (K=544, BK=32)
    gemm_vpre_bf16<<<dim3(1, 64, 4), 256>>>(csb, WfvT, preb);

    // 7. output projection + residual + layernorm
    gemm_wo<<<dim3(4, 64), 256>>>(preb, WoT, bo, agg);
    ln_kernel<<<BATCH / 8, 256>>>(x, agg, lng, lnb, out);
}